// round 13
// baseline (speedup 1.0000x reference)
#include <cuda_runtime.h>
#include <cstdint>

// ----------------------------------------------------------------------------
// HashingDiscretizer — R13.
// Verified env: keys int32, output f32 concat [out_keys | out_vals] (2*nnz),
// feature_ids == arange(F) (runtime-verified; fallbacks kept).
// R13 = R12 cell table (correctness verified) + 8 elems/thread for 2x gather
// MLP + fused single setup kernel (2 launches total).
//   gather: ONE 1-byte load per calibrated element from a per-feature
//   2048-cell table; flagged cells (~12%) do a short exact forward scan.
// ----------------------------------------------------------------------------

static constexpr int  LUT_SIZE = 65536;
static constexpr int  NBIN     = 63;
static constexpr int  ROW      = 72;        // legacy btree (fallback paths)
static constexpr int  MAX_F    = 8192;
static constexpr int  NCELL    = 2048;
static constexpr unsigned GOLDEN = 0x9E3779B9u;
static constexpr unsigned OUT_MASK_U = 0x3FFFFFu;        // (1<<22)-1

__device__ int g_is64 = 0;
__device__ int g_not_arange = 0;  // monotone 0->1 via atomicOr (deterministic)
__device__ unsigned short g_lut[LUT_SIZE];               // fallback LUT
__device__ __align__(32) float g_btree[MAX_F * ROW];     // fallback btree
__device__ __align__(16) unsigned char g_cell[MAX_F * NCELL];  // 16MB

// Monotone quantizer shared by build + runtime (forced RN, no contraction).
__device__ __forceinline__ int cell_of(float v) {
    float t = __fmul_rn(__fadd_rn(v, 5.0f), 204.8f);
    int c = (int)t;                       // trunc-toward-zero; NaN -> 0
    return min(max(c, 0), NCELL - 1);
}

// ---- K1 (fused setup): cells | probe + LUT + legacy btree ------------------
// blocks [0, cellBlocks): one warp per feature builds its 2048-cell row.
// blocks [cellBlocks, ...): LUT + arange-check + legacy btree + width probe.
__global__ void __launch_bounds__(256)
setup_kernel(const void* __restrict__ fids, const float* __restrict__ bins,
             int F, int cellBlocks, int force64) {
    if ((int)blockIdx.x < cellBlocks) {
        __shared__ int cbs[8][64];
        int wid  = threadIdx.x >> 5;
        int lane = threadIdx.x & 31;
        int f = blockIdx.x * 8 + wid;
        if (f >= F) return;
        if (lane < NBIN)      cbs[wid][lane]      = cell_of(__ldg(&bins[f * NBIN + lane]));
        if (lane + 32 < NBIN) cbs[wid][lane + 32] = cell_of(__ldg(&bins[f * NBIN + lane + 32]));
        __syncwarp();
        const int c0 = lane * 64;
        int idx = 0;
        while (idx < NBIN && cbs[wid][idx] < c0) idx++;
        unsigned char outb[64];
        #pragma unroll 16
        for (int i = 0; i < 64; i++) {
            int c = c0 + i;
            while (idx < NBIN && cbs[wid][idx] < c) idx++;
            bool flag = (idx < NBIN) && (cbs[wid][idx] == c);
            outb[i] = (unsigned char)(idx | (flag ? 0x80 : 0));
        }
        uint4* dst = (uint4*)(g_cell + (size_t)f * NCELL + c0);
        const uint4* src = (const uint4*)outb;
        dst[0] = src[0]; dst[1] = src[1]; dst[2] = src[2]; dst[3] = src[3];
        return;
    }

    int t = ((int)blockIdx.x - cellBlocks) * blockDim.x + threadIdx.x;

    const int* fw = (const int*)fids;
    const bool is64 = force64 || (fw[1] == 0 && fw[3] == 0);
    if (t == 0) g_is64 = is64 ? 1 : 0;

    const long long* f64p = (const long long*)fids;
    const int*       f32p = (const int*)fids;

    if (t < LUT_SIZE) {
        if (t < F) {
            long long fv = is64 ? f64p[t] : (long long)f32p[t];
            if (fv != (long long)t) atomicOr(&g_not_arange, 1);
        }
        long long key = (long long)t;
        int lo = 0, hi = F;
        while (lo < hi) {
            int mid = (lo + hi) >> 1;
            long long fv = is64 ? f64p[mid] : (long long)f32p[mid];
            if (fv < key) lo = mid + 1; else hi = mid;
        }
        int idx = lo < (F - 1) ? lo : (F - 1);
        long long fv = is64 ? f64p[idx] : (long long)f32p[idx];
        unsigned short v = (unsigned short)(idx & 0x7FFF);
        if (fv == key) v |= 0x8000u;
        g_lut[t] = v;
    }
    if (t < F * ROW) {                    // legacy btree for fallback paths
        int f = t / ROW;
        int j = t - f * ROW;
        const float INF = __int_as_float(0x7f800000);
        float v;
        if (j < 8) {
            v = (j < 7) ? __ldg(&bins[f * NBIN + 8 * j + 7]) : INF;
        } else {
            int q = j - 8, l = q >> 3, p = q & 7;
            v = (p < 7) ? __ldg(&bins[f * NBIN + 8 * l + p]) : INF;
        }
        g_btree[t] = v;
    }
}

// ---- generic per-element path (fallback configs + tails) -------------------
template <bool AR>
__device__ __forceinline__ void process_one(long long k, float v, int F,
                                            unsigned& okey, float& oval) {
    unsigned long long u = (unsigned long long)k;
    bool cal; int idx;
    if (AR) { cal = u < (unsigned long long)F; idx = (int)u; }
    else {
        if (u < (unsigned long long)LUT_SIZE) {
            unsigned short e = g_lut[u];
            cal = (e & 0x8000u) != 0; idx = (int)(e & 0x7FFFu);
        } else { cal = false; idx = 0; }
    }
    if (cal) {
        const float* nb = g_btree + idx * ROW;
        float4 s0 = *(const float4*)(nb);
        float4 s1 = *(const float4*)(nb + 4);
        int c = (s0.x < v) + (s0.y < v) + (s0.z < v) + (s0.w < v)
              + (s1.x < v) + (s1.y < v) + (s1.z < v) + (s1.w < v);
        const float* lf = nb + 8 + c * 8;
        float4 l0 = *(const float4*)(lf);
        float4 l1 = *(const float4*)(lf + 4);
        int bin = c * 8
              + (l0.x < v) + (l0.y < v) + (l0.z < v) + (l0.w < v)
              + (l1.x < v) + (l1.y < v) + (l1.z < v) + (l1.w < v);
        unsigned h = ((unsigned)u * GOLDEN + (unsigned)bin) * GOLDEN;
        okey = h & OUT_MASK_U; oval = 1.0f;
    } else {
        okey = (unsigned)(u & (unsigned long long)OUT_MASK_U);
        oval = v;
    }
}

// resolve one element from its cell byte (exact; rare short scan)
__device__ __forceinline__ void resolve(unsigned u, float v, unsigned byte,
                                        const float* __restrict__ bins, int F,
                                        float& okey, float& oval) {
    if (u < (unsigned)F) {
        int bin = (int)(byte & 0x7F);
        if (byte & 0x80) {
            const float* row = bins + (size_t)u * NBIN;
            while (bin < NBIN && __ldg(&row[bin]) < v) bin++;
        }
        unsigned h = (u * GOLDEN + (unsigned)bin) * GOLDEN;
        okey = (float)(h & OUT_MASK_U);
        oval = 1.0f;
    } else {
        okey = (float)(u & OUT_MASK_U);
        oval = v;
    }
}

// ---- main kernel: 8 elems/thread, batched byte gathers ---------------------
__global__ void __launch_bounds__(256)
hashing_discretizer_kernel(const void* __restrict__ keysv,
                           const float* __restrict__ valsv,
                           const float* __restrict__ bins,
                           int nnz, void* __restrict__ outv, int F) {
    const bool is64 = (g_is64 != 0);
    const bool ar   = (g_not_arange == 0);

    if (!is64 && ar) {
        const int*   keys = (const int*)keysv;
        const float* vals = valsv;
        float*       out  = (float*)outv;

        int t = blockIdx.x * blockDim.x + threadIdx.x;
        int i0 = t * 8;
        if (i0 >= nnz) return;

        if (i0 + 7 < nnz && (nnz & 3) == 0) {
            int4   ka = __ldcs((const int4*)(keys + i0));
            int4   kb = __ldcs((const int4*)(keys + i0 + 4));
            float4 va = __ldcs((const float4*)(vals + i0));
            float4 vb = __ldcs((const float4*)(vals + i0 + 4));
            unsigned u[8] = {(unsigned)ka.x, (unsigned)ka.y, (unsigned)ka.z,
                             (unsigned)ka.w, (unsigned)kb.x, (unsigned)kb.y,
                             (unsigned)kb.z, (unsigned)kb.w};
            float v[8] = {va.x, va.y, va.z, va.w, vb.x, vb.y, vb.z, vb.w};

            // phase 1: 8 independent predicated byte gathers (batched)
            unsigned byte[8];
            #pragma unroll
            for (int j = 0; j < 8; j++) {
                byte[j] = 0;
                if (u[j] < (unsigned)F)
                    byte[j] = __ldg(&g_cell[(size_t)u[j] * NCELL + cell_of(v[j])]);
            }

            // phase 2: resolve (rare flagged scans), outputs reuse regs
            float ok[8], ov[8];
            #pragma unroll
            for (int j = 0; j < 8; j++)
                resolve(u[j], v[j], byte[j], bins, F, ok[j], ov[j]);

            __stcs((float4*)(out + i0),
                   make_float4(ok[0], ok[1], ok[2], ok[3]));
            __stcs((float4*)(out + i0 + 4),
                   make_float4(ok[4], ok[5], ok[6], ok[7]));
            __stcs((float4*)(out + nnz + i0),
                   make_float4(ov[0], ov[1], ov[2], ov[3]));
            __stcs((float4*)(out + nnz + i0 + 4),
                   make_float4(ov[4], ov[5], ov[6], ov[7]));
        } else {
            int iend = (i0 + 8 < nnz) ? i0 + 8 : nnz;
            for (int i = i0; i < iend; i++) {
                unsigned okk; float ovv;
                process_one<true>((long long)keys[i], vals[i], F, okk, ovv);
                out[i] = (float)okk;
                out[nnz + i] = ovv;
            }
        }
    } else {
        // fallback configs: scalar, 8 elems/thread
        int t = blockIdx.x * blockDim.x + threadIdx.x;
        long long i0 = (long long)t * 8;
        long long total = nnz;
        if (i0 >= total) return;
        long long iend = (i0 + 8 < total) ? i0 + 8 : total;
        for (long long i = i0; i < iend; i++) {
            long long k = is64 ? ((const long long*)keysv)[i]
                               : (long long)((const int*)keysv)[i];
            unsigned okk; float ovv;
            if (ar) process_one<true >(k, valsv[i], F, okk, ovv);
            else    process_one<false>(k, valsv[i], F, okk, ovv);
            if (is64) {
                double* o = (double*)outv;
                o[i] = (double)okk; o[total + i] = (double)ovv;
            } else {
                float* o = (float*)outv;
                o[i] = (float)okk;  o[total + i] = ovv;
            }
        }
    }
}

extern "C" void kernel_launch(void* const* d_in, const int* in_sizes, int n_in,
                              void* d_out, int out_size) {
    // ---- classify inputs by element count (order-agnostic) ----
    long long s[16];
    int n = n_in < 16 ? n_in : 16;
    for (int i = 0; i < n; i++) s[i] = (long long)in_sizes[i];

    long long m1 = -1, m2 = -1;
    for (int i = 0; i < n; i++) {
        if (s[i] > m1) { m2 = m1; m1 = s[i]; }
        else if (s[i] > m2) { m2 = s[i]; }
    }

    int ik = -1, iv = -1;
    long long nnz_ll;
    int force64 = 0;
    if (m1 == m2) {
        for (int i = 0; i < n; i++)
            if (s[i] == m1) { if (ik < 0) ik = i; else if (iv < 0) iv = i; }
        nnz_ll = m1;
    } else {
        for (int i = 0; i < n; i++) {
            if (s[i] == m1 && ik < 0) ik = i;
            else if (s[i] == m1 / 2 && iv < 0) iv = i;
        }
        nnz_ll = m1 / 2;
        force64 = 1;
    }
    if (iv < 0) iv = ik;

    int ia = -1, ib = -1;
    for (int i = 0; i < n; i++) {
        if (i == ik || i == iv) continue;
        if (ia < 0) ia = i; else if (ib < 0) ib = i;
    }
    if (ib < 0) ib = ia;
    int iF = (s[ia] <= s[ib]) ? ia : ib;   // feature_ids (smaller)
    int iB = (iF == ia) ? ib : ia;         // bin_vals

    int nnz = (int)nnz_ll;
    int F = (int)(force64 ? s[iF] / 2 : s[iF]);
    if (F > MAX_F) F = MAX_F;
    if (F < 1) F = 1;

    const void*  keys = d_in[ik];
    const float* vals = (const float*)d_in[iv];
    const void*  fids = d_in[iF];
    const float* bins = (const float*)d_in[iB];

    int cellBlocks = (F + 7) / 8;
    int tabN = F * ROW;
    if (tabN < LUT_SIZE) tabN = LUT_SIZE;
    int tabBlocks = (tabN + 255) / 256;
    setup_kernel<<<cellBlocks + tabBlocks, 256>>>(fids, bins, F, cellBlocks,
                                                  force64);

    int nthreads = (nnz + 7) / 8;
    hashing_discretizer_kernel<<<(nthreads + 255) / 256, 256>>>(
        keys, vals, bins, nnz, d_out, F);
}

// round 14
// speedup vs baseline: 1.0796x; 1.0796x over previous
#include <cuda_runtime.h>
#include <cstdint>

// ----------------------------------------------------------------------------
// HashingDiscretizer — R14.
// Verified env: keys int32, output f32 concat [out_keys | out_vals] (2*nnz),
// feature_ids == arange(F) (runtime-verified; slow exact fallbacks kept).
// R14 = R13 main kernel (verified 40.5us) + gutted setup:
//   - LUT + legacy btree builds DELETED (fallbacks recompute directly)
//   - cell build packs 16 cells in registers (no local-memory spill)
//   gather: ONE 1-byte load per calibrated element from a per-feature
//   2048-cell table; flagged cells (~9%) do a short exact forward scan.
// ----------------------------------------------------------------------------

static constexpr int  NBIN     = 63;
static constexpr int  MAX_F    = 8192;
static constexpr int  NCELL    = 2048;
static constexpr unsigned GOLDEN = 0x9E3779B9u;
static constexpr unsigned OUT_MASK_U = 0x3FFFFFu;        // (1<<22)-1

__device__ int g_is64 = 0;
__device__ int g_not_arange = 0;  // monotone 0->1 via atomicOr (deterministic)
__device__ __align__(16) unsigned char g_cell[MAX_F * NCELL];  // 16MB

// Monotone quantizer shared by build + runtime (forced RN, no contraction).
__device__ __forceinline__ int cell_of(float v) {
    float t = __fmul_rn(__fadd_rn(v, 5.0f), 204.8f);
    int c = (int)t;                       // trunc-toward-zero; NaN -> 0
    return min(max(c, 0), NCELL - 1);
}

// ---- K1 (setup): cell table build + width probe + arange check -------------
// blocks [0, cellBlocks): one warp per feature builds its 2048-cell row.
// blocks [cellBlocks, ...): width probe + arange check over F entries.
__global__ void __launch_bounds__(256)
setup_kernel(const void* __restrict__ fids, const float* __restrict__ bins,
             int F, int cellBlocks, int force64) {
    if ((int)blockIdx.x < cellBlocks) {
        __shared__ int cbs[8][64];
        int wid  = threadIdx.x >> 5;
        int lane = threadIdx.x & 31;
        int f = blockIdx.x * 8 + wid;
        if (f >= F) return;
        // cell index of each boundary (ascending: bins row sorted, cell_of
        // monotone nondecreasing)
        if (lane < NBIN)      cbs[wid][lane]      = cell_of(__ldg(&bins[f * NBIN + lane]));
        if (lane + 32 < NBIN) cbs[wid][lane + 32] = cell_of(__ldg(&bins[f * NBIN + lane + 32]));
        __syncwarp();

        // lane fills cells [lane*64, lane*64+64), 16 cells per uint4 store,
        // all state in registers (no local array).
        const int* bc = cbs[wid];
        int c0 = lane * 64;
        int idx = 0;
        while (idx < NBIN && bc[idx] < c0) idx++;
        unsigned char* dst = g_cell + (size_t)f * NCELL + c0;
        #pragma unroll
        for (int chunk = 0; chunk < 4; chunk++) {
            unsigned w0 = 0, w1 = 0, w2 = 0, w3 = 0;
            int cb = c0 + chunk * 16;
            #pragma unroll
            for (int i = 0; i < 16; i++) {
                int c = cb + i;
                while (idx < NBIN && bc[idx] < c) idx++;
                unsigned byte = (unsigned)idx
                    | (((idx < NBIN) && (bc[idx] == c)) ? 0x80u : 0u);
                unsigned sh = 8u * (i & 3);
                if (i < 4)       w0 |= byte << sh;
                else if (i < 8)  w1 |= byte << sh;
                else if (i < 12) w2 |= byte << sh;
                else             w3 |= byte << sh;
            }
            *(uint4*)(dst + chunk * 16) = make_uint4(w0, w1, w2, w3);
        }
        return;
    }

    int t = ((int)blockIdx.x - cellBlocks) * blockDim.x + threadIdx.x;
    const int* fw = (const int*)fids;
    const bool is64 = force64 || (fw[1] == 0 && fw[3] == 0);
    if (t == 0) g_is64 = is64 ? 1 : 0;
    if (t < F) {
        long long fv = is64 ? ((const long long*)fids)[t]
                            : (long long)((const int*)fids)[t];
        if (fv != (long long)t) atomicOr(&g_not_arange, 1);
    }
}

// ---- slow exact fallback (non-arange / 64-bit configs; never hot here) -----
__device__ void process_fallback(long long k, float v,
                                 const void* __restrict__ fids, bool is64,
                                 const float* __restrict__ bins, int F,
                                 unsigned& okey, float& oval) {
    // lower_bound on fids
    int lo = 0, hi = F;
    while (lo < hi) {
        int mid = (lo + hi) >> 1;
        long long fv = is64 ? ((const long long*)fids)[mid]
                            : (long long)((const int*)fids)[mid];
        if (fv < k) lo = mid + 1; else hi = mid;
    }
    int idx = lo < (F - 1) ? lo : (F - 1);
    long long fv = is64 ? ((const long long*)fids)[idx]
                        : (long long)((const int*)fids)[idx];
    if (fv == k) {
        const float* row = bins + (size_t)idx * NBIN;
        int bin = 0;
        for (int j = 0; j < NBIN; j++) bin += (__ldg(&row[j]) < v) ? 1 : 0;
        unsigned h = ((unsigned)(unsigned long long)k * GOLDEN
                      + (unsigned)bin) * GOLDEN;
        okey = h & OUT_MASK_U; oval = 1.0f;
    } else {
        okey = (unsigned)((unsigned long long)k & (unsigned long long)OUT_MASK_U);
        oval = v;
    }
}

// resolve one hot-path element from its cell byte (exact; rare short scan)
__device__ __forceinline__ void resolve(unsigned u, float v, unsigned byte,
                                        const float* __restrict__ bins, int F,
                                        float& okey, float& oval) {
    if (u < (unsigned)F) {
        int bin = (int)(byte & 0x7F);
        if (byte & 0x80) {
            const float* row = bins + (size_t)u * NBIN;
            while (bin < NBIN && __ldg(&row[bin]) < v) bin++;
        }
        unsigned h = (u * GOLDEN + (unsigned)bin) * GOLDEN;
        okey = (float)(h & OUT_MASK_U);
        oval = 1.0f;
    } else {
        okey = (float)(u & OUT_MASK_U);
        oval = v;
    }
}

// ---- main kernel: 8 elems/thread, batched byte gathers ---------------------
__global__ void __launch_bounds__(256)
hashing_discretizer_kernel(const void* __restrict__ keysv,
                           const float* __restrict__ valsv,
                           const float* __restrict__ bins,
                           const void* __restrict__ fids,
                           int nnz, void* __restrict__ outv, int F) {
    const bool is64 = (g_is64 != 0);
    const bool ar   = (g_not_arange == 0);

    if (!is64 && ar) {
        const int*   keys = (const int*)keysv;
        const float* vals = valsv;
        float*       out  = (float*)outv;

        int t = blockIdx.x * blockDim.x + threadIdx.x;
        int i0 = t * 8;
        if (i0 >= nnz) return;

        if (i0 + 7 < nnz && (nnz & 3) == 0) {
            int4   ka = __ldcs((const int4*)(keys + i0));
            int4   kb = __ldcs((const int4*)(keys + i0 + 4));
            float4 va = __ldcs((const float4*)(vals + i0));
            float4 vb = __ldcs((const float4*)(vals + i0 + 4));
            unsigned u[8] = {(unsigned)ka.x, (unsigned)ka.y, (unsigned)ka.z,
                             (unsigned)ka.w, (unsigned)kb.x, (unsigned)kb.y,
                             (unsigned)kb.z, (unsigned)kb.w};
            float v[8] = {va.x, va.y, va.z, va.w, vb.x, vb.y, vb.z, vb.w};

            // phase 1: 8 independent predicated byte gathers (batched)
            unsigned byte[8];
            #pragma unroll
            for (int j = 0; j < 8; j++) {
                byte[j] = 0;
                if (u[j] < (unsigned)F)
                    byte[j] = __ldg(&g_cell[(size_t)u[j] * NCELL + cell_of(v[j])]);
            }

            // phase 2: resolve (rare flagged scans)
            float ok[8], ov[8];
            #pragma unroll
            for (int j = 0; j < 8; j++)
                resolve(u[j], v[j], byte[j], bins, F, ok[j], ov[j]);

            __stcs((float4*)(out + i0),
                   make_float4(ok[0], ok[1], ok[2], ok[3]));
            __stcs((float4*)(out + i0 + 4),
                   make_float4(ok[4], ok[5], ok[6], ok[7]));
            __stcs((float4*)(out + nnz + i0),
                   make_float4(ov[0], ov[1], ov[2], ov[3]));
            __stcs((float4*)(out + nnz + i0 + 4),
                   make_float4(ov[4], ov[5], ov[6], ov[7]));
        } else {
            int iend = (i0 + 8 < nnz) ? i0 + 8 : nnz;
            for (int i = i0; i < iend; i++) {
                unsigned u = (unsigned)keys[i];
                float vv = vals[i];
                float okk, ovv;
                unsigned byte = 0;
                if (u < (unsigned)F)
                    byte = __ldg(&g_cell[(size_t)u * NCELL + cell_of(vv)]);
                resolve(u, vv, byte, bins, F, okk, ovv);
                out[i] = okk;
                out[nnz + i] = ovv;
            }
        }
    } else {
        // fallback configs: scalar exact path, 8 elems/thread
        int t = blockIdx.x * blockDim.x + threadIdx.x;
        long long i0 = (long long)t * 8;
        long long total = nnz;
        if (i0 >= total) return;
        long long iend = (i0 + 8 < total) ? i0 + 8 : total;
        for (long long i = i0; i < iend; i++) {
            long long k = is64 ? ((const long long*)keysv)[i]
                               : (long long)((const int*)keysv)[i];
            unsigned okk; float ovv;
            process_fallback(k, valsv[i], fids, is64, bins, F, okk, ovv);
            if (is64) {
                double* o = (double*)outv;
                o[i] = (double)okk; o[total + i] = (double)ovv;
            } else {
                float* o = (float*)outv;
                o[i] = (float)okk;  o[total + i] = ovv;
            }
        }
    }
}

extern "C" void kernel_launch(void* const* d_in, const int* in_sizes, int n_in,
                              void* d_out, int out_size) {
    // ---- classify inputs by element count (order-agnostic) ----
    long long s[16];
    int n = n_in < 16 ? n_in : 16;
    for (int i = 0; i < n; i++) s[i] = (long long)in_sizes[i];

    long long m1 = -1, m2 = -1;
    for (int i = 0; i < n; i++) {
        if (s[i] > m1) { m2 = m1; m1 = s[i]; }
        else if (s[i] > m2) { m2 = s[i]; }
    }

    int ik = -1, iv = -1;
    long long nnz_ll;
    int force64 = 0;
    if (m1 == m2) {
        for (int i = 0; i < n; i++)
            if (s[i] == m1) { if (ik < 0) ik = i; else if (iv < 0) iv = i; }
        nnz_ll = m1;
    } else {
        for (int i = 0; i < n; i++) {
            if (s[i] == m1 && ik < 0) ik = i;
            else if (s[i] == m1 / 2 && iv < 0) iv = i;
        }
        nnz_ll = m1 / 2;
        force64 = 1;
    }
    if (iv < 0) iv = ik;

    int ia = -1, ib = -1;
    for (int i = 0; i < n; i++) {
        if (i == ik || i == iv) continue;
        if (ia < 0) ia = i; else if (ib < 0) ib = i;
    }
    if (ib < 0) ib = ia;
    int iF = (s[ia] <= s[ib]) ? ia : ib;   // feature_ids (smaller)
    int iB = (iF == ia) ? ib : ia;         // bin_vals

    int nnz = (int)nnz_ll;
    int F = (int)(force64 ? s[iF] / 2 : s[iF]);
    if (F > MAX_F) F = MAX_F;
    if (F < 1) F = 1;

    const void*  keys = d_in[ik];
    const float* vals = (const float*)d_in[iv];
    const void*  fids = d_in[iF];
    const float* bins = (const float*)d_in[iB];

    int cellBlocks = (F + 7) / 8;
    int probeBlocks = (F + 255) / 256;
    setup_kernel<<<cellBlocks + probeBlocks, 256>>>(fids, bins, F, cellBlocks,
                                                    force64);

    int nthreads = (nnz + 7) / 8;
    hashing_discretizer_kernel<<<(nthreads + 255) / 256, 256>>>(
        keys, vals, bins, fids, nnz, d_out, F);
}

// round 16
// speedup vs baseline: 1.1974x; 1.1091x over previous
#include <cuda_runtime.h>
#include <cstdint>

// ----------------------------------------------------------------------------
// HashingDiscretizer — R15.
// Verified env: keys int32, output f32 concat [out_keys | out_vals] (2*nnz),
// feature_ids == arange(F) (runtime-verified; slow exact fallbacks kept).
// R15 = R14 main kernel UNCHANGED (verified 39.8us) + 4x-parallel cell build:
//   one thread per 16-cell chunk (binary-search start + short walk), fully
//   coalesced 16B stores. Setup predicted ~16us -> ~5us.
//   gather: ONE 1-byte load per calibrated element from a per-feature
//   2048-cell table; flagged cells (~9%) do a short exact forward scan.
// ----------------------------------------------------------------------------

static constexpr int  NBIN     = 63;
static constexpr int  MAX_F    = 8192;
static constexpr int  NCELL    = 2048;
static constexpr unsigned GOLDEN = 0x9E3779B9u;
static constexpr unsigned OUT_MASK_U = 0x3FFFFFu;        // (1<<22)-1

__device__ int g_is64 = 0;
__device__ int g_not_arange = 0;  // monotone 0->1 via atomicOr (deterministic)
__device__ __align__(16) unsigned char g_cell[MAX_F * NCELL];  // 16MB

// Monotone quantizer shared by build + runtime (forced RN, no contraction).
__device__ __forceinline__ int cell_of(float v) {
    float t = __fmul_rn(__fadd_rn(v, 5.0f), 204.8f);
    int c = (int)t;                       // trunc-toward-zero; NaN -> 0
    return min(max(c, 0), NCELL - 1);
}

// ---- K1 (setup): cell table build + width probe + arange check -------------
// blocks [0, cellBlocks): 2 features per block; 128 threads per feature;
//   each thread builds 16 cells and does one coalesced 16B store.
// blocks [cellBlocks, ...): width probe + arange check over F entries.
__global__ void __launch_bounds__(256)
setup_kernel(const void* __restrict__ fids, const float* __restrict__ bins,
             int F, int cellBlocks, int force64) {
    if ((int)blockIdx.x < cellBlocks) {
        __shared__ int cbs[2][64];
        int sub = threadIdx.x >> 7;          // feature slot within block
        int tt  = threadIdx.x & 127;         // thread within feature
        int f = blockIdx.x * 2 + sub;
        bool active = (f < F);
        // boundary cells (ascending: bins row sorted, cell_of monotone)
        if (active && tt < NBIN)
            cbs[sub][tt] = cell_of(__ldg(&bins[f * NBIN + tt]));
        __syncthreads();
        if (!active) return;

        const int* bc = cbs[sub];
        int c0 = tt * 16;
        // lower_bound: first idx with bc[idx] >= c0   (6-step binary search)
        int lo = 0, hi = NBIN;
        while (lo < hi) {
            int mid = (lo + hi) >> 1;
            if (bc[mid] < c0) lo = mid + 1; else hi = mid;
        }
        int idx = lo;
        int cur = (idx < NBIN) ? bc[idx] : 0x7FFFFFFF;
        unsigned w0 = 0, w1 = 0, w2 = 0, w3 = 0;
        #pragma unroll
        for (int i = 0; i < 16; i++) {
            int c = c0 + i;
            while (cur < c) {
                idx++;
                cur = (idx < NBIN) ? bc[idx] : 0x7FFFFFFF;
            }
            unsigned byte = (unsigned)idx | ((cur == c) ? 0x80u : 0u);
            unsigned sh = 8u * (i & 3);
            if (i < 4)       w0 |= byte << sh;
            else if (i < 8)  w1 |= byte << sh;
            else if (i < 12) w2 |= byte << sh;
            else             w3 |= byte << sh;
        }
        *(uint4*)(g_cell + (size_t)f * NCELL + c0) = make_uint4(w0, w1, w2, w3);
        return;
    }

    int t = ((int)blockIdx.x - cellBlocks) * blockDim.x + threadIdx.x;
    const int* fw = (const int*)fids;
    const bool is64 = force64 || (fw[1] == 0 && fw[3] == 0);
    if (t == 0) g_is64 = is64 ? 1 : 0;
    if (t < F) {
        long long fv = is64 ? ((const long long*)fids)[t]
                            : (long long)((const int*)fids)[t];
        if (fv != (long long)t) atomicOr(&g_not_arange, 1);
    }
}

// ---- slow exact fallback (non-arange / 64-bit configs; never hot here) -----
__device__ void process_fallback(long long k, float v,
                                 const void* __restrict__ fids, bool is64,
                                 const float* __restrict__ bins, int F,
                                 unsigned& okey, float& oval) {
    int lo = 0, hi = F;
    while (lo < hi) {
        int mid = (lo + hi) >> 1;
        long long fv = is64 ? ((const long long*)fids)[mid]
                            : (long long)((const int*)fids)[mid];
        if (fv < k) lo = mid + 1; else hi = mid;
    }
    int idx = lo < (F - 1) ? lo : (F - 1);
    long long fv = is64 ? ((const long long*)fids)[idx]
                        : (long long)((const int*)fids)[idx];
    if (fv == k) {
        const float* row = bins + (size_t)idx * NBIN;
        int bin = 0;
        for (int j = 0; j < NBIN; j++) bin += (__ldg(&row[j]) < v) ? 1 : 0;
        unsigned h = ((unsigned)(unsigned long long)k * GOLDEN
                      + (unsigned)bin) * GOLDEN;
        okey = h & OUT_MASK_U; oval = 1.0f;
    } else {
        okey = (unsigned)((unsigned long long)k & (unsigned long long)OUT_MASK_U);
        oval = v;
    }
}

// resolve one hot-path element from its cell byte (exact; rare short scan)
__device__ __forceinline__ void resolve(unsigned u, float v, unsigned byte,
                                        const float* __restrict__ bins, int F,
                                        float& okey, float& oval) {
    if (u < (unsigned)F) {
        int bin = (int)(byte & 0x7F);
        if (byte & 0x80) {
            const float* row = bins + (size_t)u * NBIN;
            while (bin < NBIN && __ldg(&row[bin]) < v) bin++;
        }
        unsigned h = (u * GOLDEN + (unsigned)bin) * GOLDEN;
        okey = (float)(h & OUT_MASK_U);
        oval = 1.0f;
    } else {
        okey = (float)(u & OUT_MASK_U);
        oval = v;
    }
}

// ---- main kernel: 8 elems/thread, batched byte gathers (UNCHANGED) ---------
__global__ void __launch_bounds__(256)
hashing_discretizer_kernel(const void* __restrict__ keysv,
                           const float* __restrict__ valsv,
                           const float* __restrict__ bins,
                           const void* __restrict__ fids,
                           int nnz, void* __restrict__ outv, int F) {
    const bool is64 = (g_is64 != 0);
    const bool ar   = (g_not_arange == 0);

    if (!is64 && ar) {
        const int*   keys = (const int*)keysv;
        const float* vals = valsv;
        float*       out  = (float*)outv;

        int t = blockIdx.x * blockDim.x + threadIdx.x;
        int i0 = t * 8;
        if (i0 >= nnz) return;

        if (i0 + 7 < nnz && (nnz & 3) == 0) {
            int4   ka = __ldcs((const int4*)(keys + i0));
            int4   kb = __ldcs((const int4*)(keys + i0 + 4));
            float4 va = __ldcs((const float4*)(vals + i0));
            float4 vb = __ldcs((const float4*)(vals + i0 + 4));
            unsigned u[8] = {(unsigned)ka.x, (unsigned)ka.y, (unsigned)ka.z,
                             (unsigned)ka.w, (unsigned)kb.x, (unsigned)kb.y,
                             (unsigned)kb.z, (unsigned)kb.w};
            float v[8] = {va.x, va.y, va.z, va.w, vb.x, vb.y, vb.z, vb.w};

            // phase 1: 8 independent predicated byte gathers (batched)
            unsigned byte[8];
            #pragma unroll
            for (int j = 0; j < 8; j++) {
                byte[j] = 0;
                if (u[j] < (unsigned)F)
                    byte[j] = __ldg(&g_cell[(size_t)u[j] * NCELL + cell_of(v[j])]);
            }

            // phase 2: resolve (rare flagged scans)
            float ok[8], ov[8];
            #pragma unroll
            for (int j = 0; j < 8; j++)
                resolve(u[j], v[j], byte[j], bins, F, ok[j], ov[j]);

            __stcs((float4*)(out + i0),
                   make_float4(ok[0], ok[1], ok[2], ok[3]));
            __stcs((float4*)(out + i0 + 4),
                   make_float4(ok[4], ok[5], ok[6], ok[7]));
            __stcs((float4*)(out + nnz + i0),
                   make_float4(ov[0], ov[1], ov[2], ov[3]));
            __stcs((float4*)(out + nnz + i0 + 4),
                   make_float4(ov[4], ov[5], ov[6], ov[7]));
        } else {
            int iend = (i0 + 8 < nnz) ? i0 + 8 : nnz;
            for (int i = i0; i < iend; i++) {
                unsigned u = (unsigned)keys[i];
                float vv = vals[i];
                float okk, ovv;
                unsigned byte = 0;
                if (u < (unsigned)F)
                    byte = __ldg(&g_cell[(size_t)u * NCELL + cell_of(vv)]);
                resolve(u, vv, byte, bins, F, okk, ovv);
                out[i] = okk;
                out[nnz + i] = ovv;
            }
        }
    } else {
        // fallback configs: scalar exact path, 8 elems/thread
        int t = blockIdx.x * blockDim.x + threadIdx.x;
        long long i0 = (long long)t * 8;
        long long total = nnz;
        if (i0 >= total) return;
        long long iend = (i0 + 8 < total) ? i0 + 8 : total;
        for (long long i = i0; i < iend; i++) {
            long long k = is64 ? ((const long long*)keysv)[i]
                               : (long long)((const int*)keysv)[i];
            unsigned okk; float ovv;
            process_fallback(k, valsv[i], fids, is64, bins, F, okk, ovv);
            if (is64) {
                double* o = (double*)outv;
                o[i] = (double)okk; o[total + i] = (double)ovv;
            } else {
                float* o = (float*)outv;
                o[i] = (float)okk;  o[total + i] = ovv;
            }
        }
    }
}

extern "C" void kernel_launch(void* const* d_in, const int* in_sizes, int n_in,
                              void* d_out, int out_size) {
    // ---- classify inputs by element count (order-agnostic) ----
    long long s[16];
    int n = n_in < 16 ? n_in : 16;
    for (int i = 0; i < n; i++) s[i] = (long long)in_sizes[i];

    long long m1 = -1, m2 = -1;
    for (int i = 0; i < n; i++) {
        if (s[i] > m1) { m2 = m1; m1 = s[i]; }
        else if (s[i] > m2) { m2 = s[i]; }
    }

    int ik = -1, iv = -1;
    long long nnz_ll;
    int force64 = 0;
    if (m1 == m2) {
        for (int i = 0; i < n; i++)
            if (s[i] == m1) { if (ik < 0) ik = i; else if (iv < 0) iv = i; }
        nnz_ll = m1;
    } else {
        for (int i = 0; i < n; i++) {
            if (s[i] == m1 && ik < 0) ik = i;
            else if (s[i] == m1 / 2 && iv < 0) iv = i;
        }
        nnz_ll = m1 / 2;
        force64 = 1;
    }
    if (iv < 0) iv = ik;

    int ia = -1, ib = -1;
    for (int i = 0; i < n; i++) {
        if (i == ik || i == iv) continue;
        if (ia < 0) ia = i; else if (ib < 0) ib = i;
    }
    if (ib < 0) ib = ia;
    int iF = (s[ia] <= s[ib]) ? ia : ib;   // feature_ids (smaller)
    int iB = (iF == ia) ? ib : ia;         // bin_vals

    int nnz = (int)nnz_ll;
    int F = (int)(force64 ? s[iF] / 2 : s[iF]);
    if (F > MAX_F) F = MAX_F;
    if (F < 1) F = 1;

    const void*  keys = d_in[ik];
    const float* vals = (const float*)d_in[iv];
    const void*  fids = d_in[iF];
    const float* bins = (const float*)d_in[iB];

    int cellBlocks = (F + 1) / 2;          // 2 features per 256-thread block
    int probeBlocks = (F + 255) / 256;
    setup_kernel<<<cellBlocks + probeBlocks, 256>>>(fids, bins, F, cellBlocks,
                                                    force64);

    int nthreads = (nnz + 7) / 8;
    hashing_discretizer_kernel<<<(nthreads + 255) / 256, 256>>>(
        keys, vals, bins, fids, nnz, d_out, F);
}